// round 2
// baseline (speedup 1.0000x reference)
#include <cuda_runtime.h>
#include <cuda_bf16.h>

// LSEP loss, factorized:
//   S_b = (sum_{neg} e^{x}) * (sum_{pos} e^{-x});  loss = mean_b log1p(S_b)
// N = 512 rows, C = 512 cols.
// Single kernel: one warp per row (128 blocks x 4 warps), per-row results to a
// __device__ scratch array (distinct addresses -> no atomic contention), last
// finishing block reduces the 512 partials and writes the scalar output.
// No memset node needed: counter is zero-initialized and reset by the last block.

#define NROWS 512
#define NCOLS 512
#define NBLOCKS 128
#define NTHREADS 128   // 4 warps per block, 1 warp per row

__device__ float        g_row[NROWS];
__device__ unsigned int g_count;   // zero-initialized at module load; reset each run

__global__ void __launch_bounds__(NTHREADS) lsep_kernel(
    const int* __restrict__ y_true,
    const float* __restrict__ y_pred,
    float* __restrict__ out)
{
    const int warp = threadIdx.x >> 5;
    const int lane = threadIdx.x & 31;
    const int row  = blockIdx.x * 4 + warp;

    const float4* __restrict__ pv = reinterpret_cast<const float4*>(y_pred + row * NCOLS);
    const int4*   __restrict__ tv = reinterpret_cast<const int4*>(y_true + row * NCOLS);

    // 512 cols = 128 float4 per row; each lane takes 4 (stride 32) -> MLP=8 loads
    float4 v0 = pv[lane];        float4 v1 = pv[lane + 32];
    float4 v2 = pv[lane + 64];   float4 v3 = pv[lane + 96];
    int4   l0 = tv[lane];        int4   l1 = tv[lane + 32];
    int4   l2 = tv[lane + 64];   int4   l3 = tv[lane + 96];

    float pos = 0.f, neg = 0.f;

#define ACC(LBL, VAL) do {                        \
        float fl = (float)(LBL);                  \
        float e  = __expf((LBL) ? -(VAL) : (VAL));\
        pos = fmaf(fl, e, pos);                   \
        neg = fmaf(1.0f - fl, e, neg);            \
    } while (0)

    ACC(l0.x, v0.x); ACC(l0.y, v0.y); ACC(l0.z, v0.z); ACC(l0.w, v0.w);
    ACC(l1.x, v1.x); ACC(l1.y, v1.y); ACC(l1.z, v1.z); ACC(l1.w, v1.w);
    ACC(l2.x, v2.x); ACC(l2.y, v2.y); ACC(l2.z, v2.z); ACC(l2.w, v2.w);
    ACC(l3.x, v3.x); ACC(l3.y, v3.y); ACC(l3.z, v3.z); ACC(l3.w, v3.w);
#undef ACC

    // warp reduction (two independent shuffle chains, interleaved)
    #pragma unroll
    for (int off = 16; off > 0; off >>= 1) {
        pos += __shfl_xor_sync(0xFFFFFFFFu, pos, off);
        neg += __shfl_xor_sync(0xFFFFFFFFu, neg, off);
    }

    if (lane == 0) {
        g_row[row] = log1pf(pos * neg);
        __threadfence();   // make this row's result visible device-wide
    }
    __syncthreads();

    // Elect the last finishing block to do the final reduction.
    __shared__ bool s_last;
    if (threadIdx.x == 0) {
        unsigned int prev = atomicAdd(&g_count, 1u);
        s_last = (prev == NBLOCKS - 1);
    }
    __syncthreads();

    if (s_last) {
        __threadfence();   // acquire: order our reads after observing the count
        const int t = threadIdx.x;
        float s = __ldcg(&g_row[t])
                + __ldcg(&g_row[t + 128])
                + __ldcg(&g_row[t + 256])
                + __ldcg(&g_row[t + 384]);

        #pragma unroll
        for (int off = 16; off > 0; off >>= 1)
            s += __shfl_xor_sync(0xFFFFFFFFu, s, off);

        __shared__ float s_part[4];
        if ((t & 31) == 0) s_part[t >> 5] = s;
        __syncthreads();

        if (t == 0) {
            float total = s_part[0] + s_part[1] + s_part[2] + s_part[3];
            out[0] = total * (1.0f / (float)NROWS);
            g_count = 0;   // reset for next graph replay
        }
    }
}

extern "C" void kernel_launch(void* const* d_in, const int* in_sizes, int n_in,
                              void* d_out, int out_size)
{
    const int*   y_true = (const int*)d_in[0];
    const float* y_pred = (const float*)d_in[1];
    float* out = (float*)d_out;

    lsep_kernel<<<NBLOCKS, NTHREADS>>>(y_true, y_pred, out);
}